// round 5
// baseline (speedup 1.0000x reference)
#include <cuda_runtime.h>
#include <math.h>

// Problem constants (fixed by the dataset)
#define MAXN 50000
#define MAXE 600000
#define HD   128
#define OUTD 40
#define NITER 5
#define GAMMA_C 0.1f
#define EPS_C   0.1f

// ---------------- scratch (device globals: no allocation allowed) -----------
__device__ float g_h[MAXN * HD];       // current node features x
__device__ float g_neigh[MAXN * HD];   // x @ W_lin^T
__device__ float g_zb[MAXN * HD];      // x @ A^T  (bias added in agg via g_biasc)
__device__ float g_Bemb[HD * HD];      // B[k][j] = W_emb[j][k]
__device__ float g_Bc[HD * 256];       // [k][j<128]=W_lin[j][k]; [k][128+j]=A[j][k]
__device__ float g_biasc[256];         // [0..127]=0, [128..255]=b_conv
__device__ int   g_rowstart[MAXN + 1];
__device__ int   g_cursor[MAXN];
__device__ int   g_esrc[MAXE];
__device__ float g_ew[MAXE];

// ---------------- f32x2 helpers (documented sm_103a pattern) -----------------
__device__ __forceinline__ unsigned long long pack2(float a) {
    unsigned long long r;
    asm("mov.b64 %0,{%1,%1};" : "=l"(r) : "f"(a));
    return r;
}
__device__ __forceinline__ void ffma2(unsigned long long& d,
                                      unsigned long long a,
                                      unsigned long long b) {
    asm("fma.rn.f32x2 %0,%1,%2,%0;" : "+l"(d) : "l"(a), "l"(b));
}
__device__ __forceinline__ void unpack2(unsigned long long v, float& lo, float& hi) {
    asm("mov.b64 {%0,%1},%2;" : "=f"(lo), "=f"(hi) : "l"(v));
}

// ---------------- weight preprocessing --------------------------------------
__global__ void precompute_kernel(const float* __restrict__ W_emb,
                                  const float* __restrict__ W_lin,
                                  const float* __restrict__ W_anti,
                                  const float* __restrict__ b_conv) {
    int tid = blockIdx.x * blockDim.x + threadIdx.x;
    int nt  = gridDim.x * blockDim.x;
    for (int idx = tid; idx < HD * HD; idx += nt) {
        int k = idx >> 7, j = idx & 127;
        g_Bemb[k * HD + j] = W_emb[j * HD + k];
    }
    for (int idx = tid; idx < HD * 256; idx += nt) {
        int k = idx >> 8, j = idx & 255;
        float v;
        if (j < 128) {
            v = W_lin[j * HD + k];
        } else {
            int jj = j - 128;
            v = W_anti[jj * HD + k] - W_anti[k * HD + jj];
            if (jj == k) v -= GAMMA_C;
        }
        g_Bc[k * 256 + j] = v;
    }
    for (int j = tid; j < 256; j += nt)
        g_biasc[j] = (j < 128) ? 0.0f : b_conv[j - 128];
}

// ---------------- CSR build (counting sort by dst; edge_index is INT32) ------
__global__ void zero_rowstart_kernel(int n) {
    int i = blockIdx.x * blockDim.x + threadIdx.x;
    for (; i < n; i += gridDim.x * blockDim.x) g_rowstart[i] = 0;
}
__global__ void count_kernel(const int* __restrict__ ei, int E, int N) {
    int i = blockIdx.x * blockDim.x + threadIdx.x;
    for (; i < E; i += gridDim.x * blockDim.x) {
        int d = ei[E + i];                 // dst row
        if (d >= 0 && d < N) atomicAdd(&g_rowstart[d + 1], 1);
    }
}
__global__ void scan_kernel(int n) {   // single block, 1024 threads
    __shared__ int part[1024];
    int t = threadIdx.x;
    int chunk = (n + 1023) / 1024;
    int lo = t * chunk;
    int hi = min(n, lo + chunk);
    int s = 0;
    for (int i = lo; i < hi; i++) s += g_rowstart[i];
    part[t] = s;
    __syncthreads();
    for (int off = 1; off < 1024; off <<= 1) {
        int v = (t >= off) ? part[t - off] : 0;
        __syncthreads();
        part[t] += v;
        __syncthreads();
    }
    int run = (t > 0) ? part[t - 1] : 0;
    for (int i = lo; i < hi; i++) {
        run += g_rowstart[i];
        g_rowstart[i] = run;
    }
}
__global__ void cursor_copy_kernel(int n) {
    int i = blockIdx.x * blockDim.x + threadIdx.x;
    for (; i < n; i += gridDim.x * blockDim.x) g_cursor[i] = g_rowstart[i];
}
__global__ void sort_kernel(const int* __restrict__ ei,
                            const float* __restrict__ ew, int E, int N) {
    int i = blockIdx.x * blockDim.x + threadIdx.x;
    for (; i < E; i += gridDim.x * blockDim.x) {
        int d = ei[E + i];
        int s = ei[i];
        if (d < 0 || d >= N || s < 0 || s >= N) continue;
        int pos = atomicAdd(&g_cursor[d], 1);
        g_esrc[pos] = s;
        g_ew[pos]   = ew[i];
    }
}

// ---------------- FFMA2 GEMM building block ----------------------------------
// C[M x (NG*128)] = X[M x 128] @ B[128 x NG*128]
// 256 threads: tx in [0,32) covers 128 cols per group (tx*4), ty in [0,8) covers
// 8 rows each (BM=64). X reads are warp-broadcast; B reads are one contiguous
// 512B conflict-free LDS.128 sweep per warp per group. Static smem only.

// --- embedding: out = x @ W_emb^T + b_emb  -> g_h -----------------------------
__global__ void __launch_bounds__(256) embed_gemm_kernel(const float* __restrict__ X,
                                                         const float* __restrict__ bias,
                                                         int M) {
    __shared__ float sX[64 * HD];        // 32 KB
    __shared__ float sB[8 * HD];         // 4 KB chunk
    const int tid = threadIdx.x;
    const int tx = tid & 31, ty = tid >> 5;
    const int row0 = blockIdx.x * 64;

#pragma unroll
    for (int j = 0; j < 8; j++) {        // 2048 float4 of X
        int f = tid + j * 256;
        int r = f >> 5, c = (f & 31) << 2;
        float4 v = make_float4(0.f, 0.f, 0.f, 0.f);
        if (row0 + r < M) v = *(const float4*)(X + (size_t)(row0 + r) * HD + c);
        *(float4*)(sX + r * HD + c) = v;
    }

    unsigned long long acc[8][2];
#pragma unroll
    for (int i = 0; i < 8; i++) { acc[i][0] = 0ull; acc[i][1] = 0ull; }

    for (int kc = 0; kc < 16; kc++) {
        if (tid < 256) {                 // 256 float4 chunk of B
            ((float4*)sB)[tid] = ((const float4*)g_Bemb)[kc * 256 + tid];
        }
        __syncthreads();
#pragma unroll
        for (int k = 0; k < 8; k += 2) {
            float2 a2[8];
#pragma unroll
            for (int i = 0; i < 8; i++)
                a2[i] = *(const float2*)(sX + (ty * 8 + i) * HD + kc * 8 + k);
#pragma unroll
            for (int kk = 0; kk < 2; kk++) {
                ulonglong2 b0 = *(const ulonglong2*)(sB + (k + kk) * HD + tx * 4);
#pragma unroll
                for (int i = 0; i < 8; i++) {
                    unsigned long long ap = pack2(kk ? a2[i].y : a2[i].x);
                    ffma2(acc[i][0], ap, b0.x);
                    ffma2(acc[i][1], ap, b0.y);
                }
            }
        }
        __syncthreads();
    }

    float4 bs = *(const float4*)(bias + tx * 4);
#pragma unroll
    for (int i = 0; i < 8; i++) {
        int r = row0 + ty * 8 + i;
        if (r >= M) break;
        float4 v;
        unpack2(acc[i][0], v.x, v.y);
        unpack2(acc[i][1], v.z, v.w);
        v.x += bs.x; v.y += bs.y; v.z += bs.z; v.w += bs.w;
        *(float4*)(g_h + (size_t)r * HD + tx * 4) = v;
    }
}

// --- conv: g_neigh = h @ W_lin^T ; g_zb = h @ A^T -----------------------------
__global__ void __launch_bounds__(256) conv_gemm_kernel(int M) {
    __shared__ float sX[64 * HD];        // 32 KB
    __shared__ float sB[8 * 256];        // 8 KB chunk
    const int tid = threadIdx.x;
    const int tx = tid & 31, ty = tid >> 5;
    const int row0 = blockIdx.x * 64;

#pragma unroll
    for (int j = 0; j < 8; j++) {
        int f = tid + j * 256;
        int r = f >> 5, c = (f & 31) << 2;
        float4 v = make_float4(0.f, 0.f, 0.f, 0.f);
        if (row0 + r < M) v = *(const float4*)(g_h + (size_t)(row0 + r) * HD + c);
        *(float4*)(sX + r * HD + c) = v;
    }

    unsigned long long acc[8][2][2];
#pragma unroll
    for (int i = 0; i < 8; i++)
#pragma unroll
        for (int g = 0; g < 2; g++) { acc[i][g][0] = 0ull; acc[i][g][1] = 0ull; }

    for (int kc = 0; kc < 16; kc++) {
#pragma unroll
        for (int j = 0; j < 2; j++) {    // 512 float4 chunk of B
            int f = tid + j * 256;
            ((float4*)sB)[f] = ((const float4*)g_Bc)[kc * 512 + f];
        }
        __syncthreads();
#pragma unroll
        for (int k = 0; k < 8; k += 2) {
            float2 a2[8];
#pragma unroll
            for (int i = 0; i < 8; i++)
                a2[i] = *(const float2*)(sX + (ty * 8 + i) * HD + kc * 8 + k);
#pragma unroll
            for (int kk = 0; kk < 2; kk++) {
                const float* bw = sB + (k + kk) * 256 + tx * 4;
                ulonglong2 b0 = *(const ulonglong2*)(bw);
                ulonglong2 b1 = *(const ulonglong2*)(bw + 128);
#pragma unroll
                for (int i = 0; i < 8; i++) {
                    unsigned long long ap = pack2(kk ? a2[i].y : a2[i].x);
                    ffma2(acc[i][0][0], ap, b0.x);
                    ffma2(acc[i][0][1], ap, b0.y);
                    ffma2(acc[i][1][0], ap, b1.x);
                    ffma2(acc[i][1][1], ap, b1.y);
                }
            }
        }
        __syncthreads();
    }

    float4 bs = *(const float4*)(g_biasc + 128 + tx * 4);
#pragma unroll
    for (int i = 0; i < 8; i++) {
        int r = row0 + ty * 8 + i;
        if (r >= M) break;
        float4 v0, v1;
        unpack2(acc[i][0][0], v0.x, v0.y);
        unpack2(acc[i][0][1], v0.z, v0.w);
        unpack2(acc[i][1][0], v1.x, v1.y);
        unpack2(acc[i][1][1], v1.z, v1.w);
        v1.x += bs.x; v1.y += bs.y; v1.z += bs.z; v1.w += bs.w;
        *(float4*)(g_neigh + (size_t)r * HD + tx * 4) = v0;
        *(float4*)(g_zb    + (size_t)r * HD + tx * 4) = v1;
    }
}

// ---------------- aggregation + tanh residual update (warp per node) ---------
__global__ void __launch_bounds__(256) agg_update_kernel(int N) {
    int warp = (blockIdx.x * blockDim.x + threadIdx.x) >> 5;
    int lane = threadIdx.x & 31;
    if (warp >= N) return;
    const float4* neigh = (const float4*)g_neigh;
    const float4* zb    = (const float4*)g_zb;
    float4*       hv    = (float4*)g_h;

    int s = g_rowstart[warp];
    int e = g_rowstart[warp + 1];
    float4 acc = make_float4(0.f, 0.f, 0.f, 0.f);
    for (int i = s; i < e; i++) {
        int u = g_esrc[i];
        float w = g_ew[i];
        float4 v = neigh[(size_t)u * 32 + lane];
        acc.x += w * v.x; acc.y += w * v.y; acc.z += w * v.z; acc.w += w * v.w;
    }
    float4 c = zb[(size_t)warp * 32 + lane];
    c.x += acc.x; c.y += acc.y; c.z += acc.z; c.w += acc.w;
    float4 xo = hv[(size_t)warp * 32 + lane];
    xo.x += EPS_C * tanhf(c.x);
    xo.y += EPS_C * tanhf(c.y);
    xo.z += EPS_C * tanhf(c.z);
    xo.w += EPS_C * tanhf(c.w);
    hv[(size_t)warp * 32 + lane] = xo;
}

// ---------------- readout: out[M x 40] = h @ W_out^T + b_out -----------------
__global__ void __launch_bounds__(128) readout_kernel(const float* __restrict__ W,
                                                      const float* __restrict__ b,
                                                      float* __restrict__ out,
                                                      int M) {
    __shared__ float hs[32 * 132];
    __shared__ float Wt[128 * 41];
    int tid = threadIdx.x;
    int row0 = blockIdx.x * 32;
#pragma unroll
    for (int j = 0; j < 8; j++) {
        int f = tid + j * 128;            // 1024 float4
        int r = f >> 5;
        int c = (f & 31) << 2;
        float4 v = make_float4(0.f, 0.f, 0.f, 0.f);
        if (row0 + r < M) v = *(const float4*)(g_h + (size_t)(row0 + r) * HD + c);
        *(float4*)(hs + r * 132 + c) = v;
    }
    for (int f = tid; f < OUTD * HD; f += 128) {
        int c = f / HD, k = f % HD;
        Wt[k * 41 + c] = W[c * HD + k];
    }
    __syncthreads();

    int tx = tid & 7;       // 8 col groups of 5
    int ty = tid >> 3;      // 16 row groups of 2
    float acc[2][5] = {{0.f, 0.f, 0.f, 0.f, 0.f}, {0.f, 0.f, 0.f, 0.f, 0.f}};
#pragma unroll 4
    for (int k = 0; k < HD; k++) {
        float a0 = hs[(ty * 2) * 132 + k];
        float a1 = hs[(ty * 2 + 1) * 132 + k];
        const float* w = Wt + k * 41 + tx * 5;
#pragma unroll
        for (int j = 0; j < 5; j++) {
            float wv = w[j];
            acc[0][j] += a0 * wv;
            acc[1][j] += a1 * wv;
        }
    }
#pragma unroll
    for (int i = 0; i < 2; i++) {
        int r = row0 + ty * 2 + i;
        if (r < M) {
#pragma unroll
            for (int j = 0; j < 5; j++)
                out[(size_t)r * OUTD + tx * 5 + j] = acc[i][j] + b[tx * 5 + j];
        }
    }
}

// ---------------- launch ------------------------------------------------------
extern "C" void kernel_launch(void* const* d_in, const int* in_sizes, int n_in,
                              void* d_out, int out_size) {
    const float* x      = (const float*)d_in[0];
    const int*   ei     = (const int*)d_in[1];     // int32! (JAX x64 disabled)
    const float* ew     = (const float*)d_in[2];
    const float* W_emb  = (const float*)d_in[3];
    const float* b_emb  = (const float*)d_in[4];
    const float* W_lin  = (const float*)d_in[5];
    const float* W_anti = (const float*)d_in[6];
    const float* b_conv = (const float*)d_in[7];
    const float* W_out  = (const float*)d_in[8];
    const float* b_out  = (const float*)d_in[9];
    float*       out    = (float*)d_out;

    const int M = in_sizes[0] / HD;   // N nodes
    const int E = in_sizes[2];        // edge count

    // weight preprocessing + CSR build (once per launch)
    precompute_kernel<<<64, 256>>>(W_emb, W_lin, W_anti, b_conv);
    zero_rowstart_kernel<<<128, 256>>>(M + 1);
    count_kernel<<<(E + 255) / 256, 256>>>(ei, E, M);
    scan_kernel<<<1, 1024>>>(M + 1);
    cursor_copy_kernel<<<128, 256>>>(M);
    sort_kernel<<<(E + 255) / 256, 256>>>(ei, ew, E, M);

    const int gb = (M + 63) / 64;

    // embedding
    embed_gemm_kernel<<<gb, 256>>>(x, b_emb, M);

    // 5 diffusion steps
    for (int it = 0; it < NITER; it++) {
        conv_gemm_kernel<<<gb, 256>>>(M);
        agg_update_kernel<<<(M + 7) / 8, 256>>>(M);
    }

    // readout
    readout_kernel<<<(M + 31) / 32, 128>>>(W_out, b_out, out, M);
}